// round 5
// baseline (speedup 1.0000x reference)
#include <cuda_runtime.h>
#include <cuda_bf16.h>

// Problem constants (fixed by reference setup_inputs)
#define BATCH 16
#define CIN   128
#define COUT  128
#define HH    128
#define WW    128
#define SS    512
#define KK    3
#define EPS   1e-8f

// Scratch (allocation-free: __device__ globals)
__device__ float g_s[BATCH * CIN];        // modulation scale per (b, ci)
__device__ float g_wsq[COUT * CIN];       // sum_k weight^2 per (co, ci)
__device__ float g_decoef[BATCH * COUT];  // demodulation per (b, co)

// ---------------------------------------------------------------------------
// Setup kernel 1: s[b][ci] = style[b] . mod_w[ci] + mod_b[ci]
// 2048 threads total
__global__ void k_modscale(const float* __restrict__ style,
                           const float* __restrict__ mod_w,
                           const float* __restrict__ mod_b) {
    int t = blockIdx.x * blockDim.x + threadIdx.x;
    if (t >= BATCH * CIN) return;
    int b = t >> 7;           // /128
    int ci = t & 127;
    const float* st = style + b * SS;
    const float* mw = mod_w + ci * SS;
    float acc = 0.f;
#pragma unroll 8
    for (int j = 0; j < SS; ++j) acc = fmaf(st[j], mw[j], acc);
    g_s[t] = acc + mod_b[ci];
}

// Setup kernel 2: wsq[co][ci] = sum_k weight[co,ci,k]^2
__global__ void k_wsq(const float* __restrict__ weight) {
    int t = blockIdx.x * blockDim.x + threadIdx.x;
    if (t >= COUT * CIN) return;
    const float* w = weight + t * (KK * KK);
    float acc = 0.f;
#pragma unroll
    for (int k = 0; k < KK * KK; ++k) acc = fmaf(w[k], w[k], acc);
    g_wsq[t] = acc;
}

// Setup kernel 3: decoef[b][co] = rsqrt(sum_ci wsq[co,ci]*s[b,ci]^2 + eps)
__global__ void k_decoef() {
    int t = blockIdx.x * blockDim.x + threadIdx.x;
    if (t >= BATCH * COUT) return;
    int b = t >> 7;
    int co = t & 127;
    const float* sv = g_s + b * CIN;
    const float* wq = g_wsq + co * CIN;
    float acc = 0.f;
#pragma unroll 8
    for (int ci = 0; ci < CIN; ++ci) {
        float s = sv[ci];
        acc = fmaf(wq[ci], s * s, acc);
    }
    g_decoef[t] = rsqrtf(acc + EPS);
}

// ---------------------------------------------------------------------------
// Main conv kernel.
// out[b,co,y,x] = decoef[b,co] * sum_{ci,kh,kw} weight[co,ci,kh,kw] * (s[b,ci]*x[b,ci,y+kh-1,x+kw-1])
//
// CTA: one batch b, 32 output channels, 16x16 spatial tile.
// Threads: 256. co_grp = tid>>5 (8 groups of 4 channels), px = tid&31,
// each thread computes 4 co x 8 px (one row-of-8 segment).
#define CO_T   32
#define TILE   16
#define CI_T   8
#define XPITCH 20           // row pitch in floats for x tile (18 used)

__global__ __launch_bounds__(256, 2)
void k_conv(const float* __restrict__ x,
            const float* __restrict__ weight,
            float* __restrict__ out) {
    __shared__ float xs[CI_T][18 * XPITCH];       // scaled input tile + halo
    __shared__ float ws[CO_T * CI_T * 9];         // raw weights chunk

    const int tid = threadIdx.x;
    const int b  = blockIdx.z;
    const int co_base = blockIdx.y * CO_T;
    const int h0 = (blockIdx.x >> 3) * TILE;
    const int w0 = (blockIdx.x & 7) * TILE;

    const int co_grp = tid >> 5;        // 0..7
    const int px = tid & 31;
    const int r  = px >> 1;             // output row within tile 0..15
    const int c8 = (px & 1) * 8;        // output col segment base (0 or 8)

    float acc[4][8];
#pragma unroll
    for (int i = 0; i < 4; ++i)
#pragma unroll
        for (int j = 0; j < 8; ++j) acc[i][j] = 0.f;

    for (int c0 = 0; c0 < CIN; c0 += CI_T) {
        // ---- stage x tile (scaled by s) ----
        for (int i = tid; i < CI_T * 18 * 18; i += 256) {
            int ci = i / 324;
            int rem = i - ci * 324;
            int y = rem / 18;
            int xx = rem - y * 18;
            int gy = h0 - 1 + y;
            int gx = w0 - 1 + xx;
            float v = 0.f;
            if (gy >= 0 && gy < HH && gx >= 0 && gx < WW)
                v = x[(((size_t)b * CIN + c0 + ci) * HH + gy) * WW + gx];
            xs[ci][y * XPITCH + xx] = v * g_s[b * CIN + c0 + ci];
        }
        // ---- stage weights chunk ----
        for (int i = tid; i < CO_T * CI_T * 9; i += 256) {
            int co_l = i / (CI_T * 9);
            int rem  = i - co_l * (CI_T * 9);
            int ci_l = rem / 9;
            int k    = rem - ci_l * 9;
            ws[i] = weight[(((co_base + co_l) * CIN) + c0 + ci_l) * 9 + k];
        }
        __syncthreads();

        // ---- compute ----
#pragma unroll 4
        for (int ci = 0; ci < CI_T; ++ci) {
#pragma unroll
            for (int kh = 0; kh < 3; ++kh) {
                // weights for this (ci,kh): warp-uniform -> broadcast LDS
                float wv[4][3];
#pragma unroll
                for (int c4 = 0; c4 < 4; ++c4)
#pragma unroll
                    for (int kw = 0; kw < 3; ++kw)
                        wv[c4][kw] = ws[(co_grp * 4 + c4) * (CI_T * 9) + ci * 9 + kh * 3 + kw];
                // x row segment: 10 values cover all 3 kw shifts
                float xr[10];
                const float* xrow = &xs[ci][(r + kh) * XPITCH + c8];
#pragma unroll
                for (int j = 0; j < 10; ++j) xr[j] = xrow[j];
#pragma unroll
                for (int kw = 0; kw < 3; ++kw)
#pragma unroll
                    for (int c4 = 0; c4 < 4; ++c4)
#pragma unroll
                        for (int j = 0; j < 8; ++j)
                            acc[c4][j] = fmaf(wv[c4][kw], xr[j + kw], acc[c4][j]);
            }
        }
        __syncthreads();
    }

    // ---- store with demodulation ----
#pragma unroll
    for (int c4 = 0; c4 < 4; ++c4) {
        int co = co_base + co_grp * 4 + c4;
        float dc = g_decoef[b * COUT + co];
        float* op = out + (((size_t)b * COUT + co) * HH + (h0 + r)) * WW + w0 + c8;
#pragma unroll
        for (int j = 0; j < 8; ++j) op[j] = acc[c4][j] * dc;
    }
}

// ---------------------------------------------------------------------------
extern "C" void kernel_launch(void* const* d_in, const int* in_sizes, int n_in,
                              void* d_out, int out_size) {
    const float* x      = (const float*)d_in[0];
    const float* style  = (const float*)d_in[1];
    const float* weight = (const float*)d_in[2];
    const float* mod_w  = (const float*)d_in[3];
    const float* mod_b  = (const float*)d_in[4];
    float* out = (float*)d_out;

    k_modscale<<<(BATCH * CIN + 255) / 256, 256>>>(style, mod_w, mod_b);
    k_wsq<<<(COUT * CIN + 255) / 256, 256>>>(weight);
    k_decoef<<<(BATCH * COUT + 255) / 256, 256>>>();

    dim3 grid((HH / TILE) * (WW / TILE), COUT / CO_T, BATCH);
    k_conv<<<grid, 256>>>(x, weight, out);
}